// round 1
// baseline (speedup 1.0000x reference)
#include <cuda_runtime.h>
#include <math.h>

#define IMG_W 2048
#define IMG_H 2048
#define RANKS 128
#define KSZ   101
#define KHALF 50
#define NCH   3

// -------- scratch (no allocations allowed; __device__ globals are the sanctioned path) --------
__device__ float g_kw[KSZ];
__device__ float g_r1b[NCH * RANKS * IMG_W];   // blurred rank1, [c][r][w]
__device__ float g_r2b[NCH * RANKS * IMG_H];   // blurred rank2, [c][r][h]
__device__ float g_img[NCH * IMG_H * IMG_W];   // channel-interleaved [h][w][c], 48 MB

// =====================================================================
// K1: Gaussian difference kernel weights from device scalar sigma
// =====================================================================
__global__ void k_gauss(const float* __restrict__ sigma_p) {
    int i = threadIdx.x;
    if (i >= KSZ) return;
    float sigma = *sigma_p;
    float s   = fmaxf(sigma, 0.01f);
    float amp = 1.0f / fmaxf(sigma * 2.50662827463100050242f, 1.0f); // sqrt(2*pi)
    float n = (float)(i - KHALF);
    float t = n / s;
    g_kw[i] = amp * expf(-0.5f * t * t);
}

// =====================================================================
// K2: 1D blur (SAME, zero pad). One block per row (c*RANKS + r), row in smem.
//     which==0 -> write g_r1b, which==1 -> write g_r2b
// =====================================================================
__global__ void k_blur(const float* __restrict__ in, int which) {
    __shared__ float srow[IMG_W];
    __shared__ float skw[KSZ];
    const int row = blockIdx.x;
    const float* rp = in + (size_t)row * IMG_W;
    for (int i = threadIdx.x; i < IMG_W; i += blockDim.x) srow[i] = rp[i];
    for (int i = threadIdx.x; i < KSZ;   i += blockDim.x) skw[i]  = g_kw[i];
    __syncthreads();
    float* out = (which == 0 ? g_r1b : g_r2b) + (size_t)row * IMG_W;
    for (int w = threadIdx.x; w < IMG_W; w += blockDim.x) {
        int lo = max(0, w - KHALF);
        int hi = min(IMG_W - 1, w + KHALF);
        float acc = 0.0f;
        #pragma unroll 4
        for (int idx = lo; idx <= hi; ++idx)
            acc = fmaf(skw[idx - w + KHALF], srow[idx], acc);
        out[w] = acc;
    }
}

// =====================================================================
// K3: per-channel SGEMM: img[c][h][w] = sum_r r2b[c][r][h] * r1b[c][r][w]
//     M = H rows, N = W cols, K = 128. Block tile 128x128, BK=8, 8x8/thread.
//     Epilogue writes channel-interleaved: g_img[(h*W + w)*3 + c]
// =====================================================================
#define BM 128
#define BN 128
#define BK 8
#define TM 8
#define TN 8

__global__ __launch_bounds__(256) void k_gemm() {
    const int c  = blockIdx.z;
    const float* A = g_r2b + (size_t)c * RANKS * IMG_H; // [r][h] K-major
    const float* B = g_r1b + (size_t)c * RANKS * IMG_W; // [r][w] K-major

    __shared__ float As[BK][BM];
    __shared__ float Bs[BK][BN];

    const int tid = threadIdx.x;
    const int m0 = blockIdx.y * BM;
    const int n0 = blockIdx.x * BN;
    const int tr = tid >> 4;   // 0..15
    const int tc = tid & 15;   // 0..15

    float acc[TM][TN];
    #pragma unroll
    for (int i = 0; i < TM; i++)
        #pragma unroll
        for (int j = 0; j < TN; j++) acc[i][j] = 0.0f;

    for (int kt = 0; kt < RANKS; kt += BK) {
        // 256 threads load 1024 floats per tile (4 each), coalesced along m/n
        #pragma unroll
        for (int i = 0; i < 4; i++) {
            int idx = tid + i * 256;
            int kk = idx >> 7;
            int mm = idx & 127;
            As[kk][mm] = A[(size_t)(kt + kk) * IMG_H + (m0 + mm)];
            Bs[kk][mm] = B[(size_t)(kt + kk) * IMG_W + (n0 + mm)];
        }
        __syncthreads();
        #pragma unroll
        for (int kk = 0; kk < BK; kk++) {
            float af[TM], bf[TN];
            #pragma unroll
            for (int i = 0; i < TM; i++) af[i] = As[kk][tr * TM + i];
            #pragma unroll
            for (int j = 0; j < TN; j++) bf[j] = Bs[kk][tc * TN + j];
            #pragma unroll
            for (int i = 0; i < TM; i++)
                #pragma unroll
                for (int j = 0; j < TN; j++)
                    acc[i][j] = fmaf(af[i], bf[j], acc[i][j]);
        }
        __syncthreads();
    }

    // interleaved epilogue
    #pragma unroll
    for (int i = 0; i < TM; i++) {
        int m = m0 + tr * TM + i;
        #pragma unroll
        for (int j = 0; j < TN; j++) {
            int n = n0 + tc * TN + j;
            g_img[((size_t)m * IMG_W + n) * NCH + c] = acc[i][j];
        }
    }
}

// =====================================================================
// K4: bilinear grid sample; one thread per point. out[p*3 + c]
// =====================================================================
__global__ __launch_bounds__(256) void k_sample(const float* __restrict__ coord,
                                                float* __restrict__ out, int npts) {
    int p = blockIdx.x * blockDim.x + threadIdx.x;
    if (p >= npts) return;

    float2 g = reinterpret_cast<const float2*>(coord)[p];
    float x = (g.x + 1.0f) * (IMG_W * 0.5f) - 0.5f;
    float y = (g.y + 1.0f) * (IMG_H * 0.5f) - 0.5f;
    float x0f = floorf(x), y0f = floorf(y);
    float wx1 = x - x0f, wy1 = y - y0f;
    float wx0 = 1.0f - wx1, wy0 = 1.0f - wy1;

    int x0 = (int)x0f, y0 = (int)y0f;
    int x1 = x0 + 1,  y1 = y0 + 1;

    float vx0 = (x0 >= 0 && x0 < IMG_W) ? 1.0f : 0.0f;
    float vx1 = (x1 >= 0 && x1 < IMG_W) ? 1.0f : 0.0f;
    float vy0 = (y0 >= 0 && y0 < IMG_H) ? 1.0f : 0.0f;
    float vy1 = (y1 >= 0 && y1 < IMG_H) ? 1.0f : 0.0f;

    int cx0 = min(max(x0, 0), IMG_W - 1);
    int cx1 = min(max(x1, 0), IMG_W - 1);
    int cy0 = min(max(y0, 0), IMG_H - 1);
    int cy1 = min(max(y1, 0), IMG_H - 1);

    float w00 = wx0 * vx0 * wy0 * vy0;
    float w10 = wx1 * vx1 * wy0 * vy0;
    float w01 = wx0 * vx0 * wy1 * vy1;
    float w11 = wx1 * vx1 * wy1 * vy1;

    const float* t00 = g_img + ((size_t)cy0 * IMG_W + cx0) * NCH;
    const float* t10 = g_img + ((size_t)cy0 * IMG_W + cx1) * NCH;
    const float* t01 = g_img + ((size_t)cy1 * IMG_W + cx0) * NCH;
    const float* t11 = g_img + ((size_t)cy1 * IMG_W + cx1) * NCH;

    #pragma unroll
    for (int ch = 0; ch < NCH; ch++) {
        float v = w00 * t00[ch] + w10 * t10[ch] + w01 * t01[ch] + w11 * t11[ch];
        out[(size_t)p * NCH + ch] = v;
    }
}

// =====================================================================
extern "C" void kernel_launch(void* const* d_in, const int* in_sizes, int n_in,
                              void* d_out, int out_size) {
    const float* rank1 = (const float*)d_in[0];   // (3,128,2048)
    const float* rank2 = (const float*)d_in[1];   // (3,128,2048)
    const float* sigma = (const float*)d_in[2];   // scalar
    const float* coord = (const float*)d_in[3];   // (8,262144,2)
    float* out = (float*)d_out;

    const int npts = in_sizes[3] / 2;             // 2,097,152

    k_gauss<<<1, 128>>>(sigma);

    k_blur<<<NCH * RANKS, 256>>>(rank1, 0);
    k_blur<<<NCH * RANKS, 256>>>(rank2, 1);

    dim3 ggrid(IMG_W / BN, IMG_H / BM, NCH);
    k_gemm<<<ggrid, 256>>>();

    k_sample<<<(npts + 255) / 256, 256>>>(coord, out, npts);
    (void)n_in; (void)out_size;
}

// round 4
// speedup vs baseline: 1.4754x; 1.4754x over previous
#include <cuda_runtime.h>
#include <cuda_bf16.h>
#include <math.h>
#include <stdint.h>

#define IMG_W 2048
#define IMG_H 2048
#define RANKS 128
#define KSZ   101
#define KHALF 50

// ---------------- scratch (__device__ globals; no allocation allowed) ----------------
__device__ float g_kw[KSZ];
__device__ float g_r1b[3 * RANKS * IMG_W];            // blurred rank1 fp32 [c][r][w]
__device__ float g_r2b[3 * RANKS * IMG_H];            // blurred rank2 fp32 [c][r][h]
// transposed bf16 hi/lo factors, K-contiguous: [c][x][r]
__device__ __nv_bfloat16 g_Bt_hi[3 * IMG_W * RANKS];  // from rank1 (w axis) -> GEMM B
__device__ __nv_bfloat16 g_Bt_lo[3 * IMG_W * RANKS];
__device__ __nv_bfloat16 g_At_hi[3 * IMG_H * RANKS];  // from rank2 (h axis) -> GEMM A
__device__ __nv_bfloat16 g_At_lo[3 * IMG_H * RANKS];
__device__ float g_img4[(size_t)IMG_H * IMG_W * 4];   // padded interleaved [h][w][4]

__device__ __forceinline__ uint32_t smem_u32(const void* p) {
    uint32_t a;
    asm("{ .reg .u64 t; cvta.to.shared.u64 t, %1; cvt.u32.u64 %0, t; }" : "=r"(a) : "l"(p));
    return a;
}

// =====================================================================
// K1: Gaussian kernel weights from device scalar sigma
// =====================================================================
__global__ void k_gauss(const float* __restrict__ sigma_p) {
    int i = threadIdx.x;
    if (i >= KSZ) return;
    float sigma = *sigma_p;
    float s   = fmaxf(sigma, 0.01f);
    float amp = 1.0f / fmaxf(sigma * 2.50662827463100050242f, 1.0f);
    float n = (float)(i - KHALF);
    float t = n / s;
    g_kw[i] = amp * expf(-0.5f * t * t);
}

// =====================================================================
// K2: 1D blur (SAME, zero pad). One block per row (c*RANKS + r).
// =====================================================================
__global__ void k_blur(const float* __restrict__ in, int which) {
    __shared__ float srow[IMG_W];
    __shared__ float skw[KSZ];
    const int row = blockIdx.x;
    const float* rp = in + (size_t)row * IMG_W;
    for (int i = threadIdx.x; i < IMG_W; i += blockDim.x) srow[i] = rp[i];
    for (int i = threadIdx.x; i < KSZ;   i += blockDim.x) skw[i]  = g_kw[i];
    __syncthreads();
    float* out = (which == 0 ? g_r1b : g_r2b) + (size_t)row * IMG_W;
    for (int w = threadIdx.x; w < IMG_W; w += blockDim.x) {
        int lo = max(0, w - KHALF);
        int hi = min(IMG_W - 1, w + KHALF);
        float acc = 0.0f;
        #pragma unroll 4
        for (int idx = lo; idx <= hi; ++idx)
            acc = fmaf(skw[idx - w + KHALF], srow[idx], acc);
        out[w] = acc;
    }
}

// =====================================================================
// K2b: transpose + bf16 hi/lo split. [c][r][x] fp32 -> [c][x][r] bf16 hi/lo
// =====================================================================
__global__ __launch_bounds__(256) void k_split_t(int which) {
    __shared__ float t[32][33];
    const int c  = blockIdx.z;
    const int x0 = blockIdx.x * 32;
    const int r0 = blockIdx.y * 32;
    const float* src = (which ? g_r2b : g_r1b) + (size_t)c * RANKS * IMG_W;
    __nv_bfloat16* dhi = (which ? g_At_hi : g_Bt_hi) + (size_t)c * IMG_W * RANKS;
    __nv_bfloat16* dlo = (which ? g_At_lo : g_Bt_lo) + (size_t)c * IMG_W * RANKS;

    const int tx = threadIdx.x;        // 0..31
    const int ty = threadIdx.y;        // 0..7
    #pragma unroll
    for (int i = 0; i < 32; i += 8)
        t[ty + i][tx] = src[(size_t)(r0 + ty + i) * IMG_W + (x0 + tx)];
    __syncthreads();
    #pragma unroll
    for (int i = 0; i < 32; i += 8) {
        float v = t[tx][ty + i];                    // (r = r0+tx, x = x0+ty+i)
        __nv_bfloat16 hi = __float2bfloat16(v);
        float rem = v - __bfloat162float(hi);
        __nv_bfloat16 lo = __float2bfloat16(rem);
        size_t o = (size_t)(x0 + ty + i) * RANKS + (r0 + tx);
        dhi[o] = hi;
        dlo[o] = lo;
    }
}

// =====================================================================
// K3: mma.sync bf16 GEMM (hi/lo split, fp32 accum).
// Block 128(M=h) x 64(N=w), K=128 resident. 8 warps as 4(m) x 2(n),
// warp tile 32x32 -> 2(m16) x 4(n8) mmas per k-step, 8 k-steps, 3 passes.
// =====================================================================
#define KP 136                      // padded smem stride in bf16 (272B, 16B-aligned)
#define SA_HI 0
#define SA_LO 34816
#define SB_HI 69632
#define SB_LO 87040
#define SM_TOTAL 104448

__device__ __forceinline__ void ldm_x4(uint32_t* r, uint32_t addr) {
    asm volatile("ldmatrix.sync.aligned.m8n8.x4.shared.b16 {%0,%1,%2,%3}, [%4];"
                 : "=r"(r[0]), "=r"(r[1]), "=r"(r[2]), "=r"(r[3]) : "r"(addr));
}
__device__ __forceinline__ void mma_bf16(float* d, const uint32_t* a, uint32_t b0, uint32_t b1) {
    asm volatile(
        "mma.sync.aligned.m16n8k16.row.col.f32.bf16.bf16.f32 "
        "{%0,%1,%2,%3}, {%4,%5,%6,%7}, {%8,%9}, {%0,%1,%2,%3};"
        : "+f"(d[0]), "+f"(d[1]), "+f"(d[2]), "+f"(d[3])
        : "r"(a[0]), "r"(a[1]), "r"(a[2]), "r"(a[3]), "r"(b0), "r"(b1));
}

__global__ __launch_bounds__(256, 2) void k_mma_gemm() {
    extern __shared__ char smem[];
    const uint32_t sb = smem_u32(smem);
    const int tid  = threadIdx.x;
    const int wid  = tid >> 5;
    const int lane = tid & 31;
    const int mw = wid & 3;          // 4 m-warps (32 rows each)
    const int nw = wid >> 2;         // 2 n-warps (32 cols each)
    const int c  = blockIdx.z;
    const int n0 = blockIdx.x * 64;
    const int m0 = blockIdx.y * 128;

    // ---- load tiles into padded smem (16B chunks) ----
    {
        const uint4* srcAh = (const uint4*)(g_At_hi + ((size_t)(c * IMG_H + m0)) * RANKS);
        const uint4* srcAl = (const uint4*)(g_At_lo + ((size_t)(c * IMG_H + m0)) * RANKS);
        const uint4* srcBh = (const uint4*)(g_Bt_hi + ((size_t)(c * IMG_W + n0)) * RANKS);
        const uint4* srcBl = (const uint4*)(g_Bt_lo + ((size_t)(c * IMG_W + n0)) * RANKS);
        #pragma unroll
        for (int it = 0; it < 8; it++) {           // A: 128 rows * 16 chunks
            int idx = tid + it * 256;
            int row = idx >> 4, ch = idx & 15;
            uint32_t off = (uint32_t)row * (KP * 2) + ch * 16;
            *(uint4*)(smem + SA_HI + off) = srcAh[(size_t)row * 16 + ch];
            *(uint4*)(smem + SA_LO + off) = srcAl[(size_t)row * 16 + ch];
        }
        #pragma unroll
        for (int it = 0; it < 4; it++) {           // B: 64 rows * 16 chunks
            int idx = tid + it * 256;
            int row = idx >> 4, ch = idx & 15;
            uint32_t off = (uint32_t)row * (KP * 2) + ch * 16;
            *(uint4*)(smem + SB_HI + off) = srcBh[(size_t)row * 16 + ch];
            *(uint4*)(smem + SB_LO + off) = srcBl[(size_t)row * 16 + ch];
        }
    }
    __syncthreads();

    float d[2][4][4];
    #pragma unroll
    for (int i = 0; i < 2; i++)
        #pragma unroll
        for (int j = 0; j < 4; j++)
            #pragma unroll
            for (int r = 0; r < 4; r++) d[i][j][r] = 0.0f;

    // per-lane ldmatrix row components (k0 added in loop)
    const int a_row = (lane & 15);           // within m-tile
    const int a_ko  = (lane >> 4) * 8;
    const int quad  = lane >> 3;
    const int b_row = ((quad >> 1) * 8) + (lane & 7);   // within 16-row n-pair
    const int b_ko  = (quad & 1) * 8;

    #pragma unroll
    for (int pass = 0; pass < 3; pass++) {
        const uint32_t aBase = sb + (pass == 2 ? SA_LO : SA_HI);
        const uint32_t bBase = sb + (pass == 1 ? SB_LO : SB_HI);
        #pragma unroll
        for (int ks = 0; ks < 8; ks++) {
            const int k0 = ks * 16;
            uint32_t af[2][4], bf[2][4];
            #pragma unroll
            for (int mt = 0; mt < 2; mt++) {
                uint32_t addr = aBase +
                    ((uint32_t)(mw * 32 + mt * 16 + a_row) * KP + k0 + a_ko) * 2;
                ldm_x4(af[mt], addr);
            }
            #pragma unroll
            for (int bp = 0; bp < 2; bp++) {
                uint32_t addr = bBase +
                    ((uint32_t)(nw * 32 + bp * 16 + b_row) * KP + k0 + b_ko) * 2;
                ldm_x4(bf[bp], addr);
            }
            #pragma unroll
            for (int mt = 0; mt < 2; mt++)
                #pragma unroll
                for (int nt = 0; nt < 4; nt++)
                    mma_bf16(d[mt][nt], af[mt], bf[nt >> 1][(nt & 1) * 2],
                             bf[nt >> 1][(nt & 1) * 2 + 1]);
        }
    }

    // ---- epilogue: write channel-interleaved image ----
    const int g = lane >> 2;
    const int t = lane & 3;
    #pragma unroll
    for (int mt = 0; mt < 2; mt++) {
        #pragma unroll
        for (int nt = 0; nt < 4; nt++) {
            int m = m0 + mw * 32 + mt * 16 + g;
            int n = n0 + nw * 32 + nt * 8 + t * 2;
            float* p0 = g_img4 + ((size_t)m * IMG_W + n) * 4 + c;
            p0[0] = d[mt][nt][0];
            p0[4] = d[mt][nt][1];
            float* p1 = g_img4 + ((size_t)(m + 8) * IMG_W + n) * 4 + c;
            p1[0] = d[mt][nt][2];
            p1[4] = d[mt][nt][3];
        }
    }
}

// =====================================================================
// K4: bilinear grid sample; float4 taps from padded image
// =====================================================================
__global__ __launch_bounds__(256) void k_sample(const float* __restrict__ coord,
                                                float* __restrict__ out, int npts) {
    int p = blockIdx.x * blockDim.x + threadIdx.x;
    if (p >= npts) return;

    float2 gxy = reinterpret_cast<const float2*>(coord)[p];
    float x = (gxy.x + 1.0f) * (IMG_W * 0.5f) - 0.5f;
    float y = (gxy.y + 1.0f) * (IMG_H * 0.5f) - 0.5f;
    float x0f = floorf(x), y0f = floorf(y);
    float wx1 = x - x0f, wy1 = y - y0f;
    float wx0 = 1.0f - wx1, wy0 = 1.0f - wy1;

    int x0 = (int)x0f, y0 = (int)y0f;
    int x1 = x0 + 1,  y1 = y0 + 1;

    float vx0 = (x0 >= 0 && x0 < IMG_W) ? 1.0f : 0.0f;
    float vx1 = (x1 >= 0 && x1 < IMG_W) ? 1.0f : 0.0f;
    float vy0 = (y0 >= 0 && y0 < IMG_H) ? 1.0f : 0.0f;
    float vy1 = (y1 >= 0 && y1 < IMG_H) ? 1.0f : 0.0f;

    int cx0 = min(max(x0, 0), IMG_W - 1);
    int cx1 = min(max(x1, 0), IMG_W - 1);
    int cy0 = min(max(y0, 0), IMG_H - 1);
    int cy1 = min(max(y1, 0), IMG_H - 1);

    float w00 = wx0 * vx0 * wy0 * vy0;
    float w10 = wx1 * vx1 * wy0 * vy0;
    float w01 = wx0 * vx0 * wy1 * vy1;
    float w11 = wx1 * vx1 * wy1 * vy1;

    const float4* img = (const float4*)g_img4;
    float4 v00 = __ldg(&img[(size_t)cy0 * IMG_W + cx0]);
    float4 v10 = __ldg(&img[(size_t)cy0 * IMG_W + cx1]);
    float4 v01 = __ldg(&img[(size_t)cy1 * IMG_W + cx0]);
    float4 v11 = __ldg(&img[(size_t)cy1 * IMG_W + cx1]);

    out[(size_t)p * 3 + 0] = w00 * v00.x + w10 * v10.x + w01 * v01.x + w11 * v11.x;
    out[(size_t)p * 3 + 1] = w00 * v00.y + w10 * v10.y + w01 * v01.y + w11 * v11.y;
    out[(size_t)p * 3 + 2] = w00 * v00.z + w10 * v10.z + w01 * v01.z + w11 * v11.z;
}

// =====================================================================
extern "C" void kernel_launch(void* const* d_in, const int* in_sizes, int n_in,
                              void* d_out, int out_size) {
    const float* rank1 = (const float*)d_in[0];
    const float* rank2 = (const float*)d_in[1];
    const float* sigma = (const float*)d_in[2];
    const float* coord = (const float*)d_in[3];
    float* out = (float*)d_out;

    const int npts = in_sizes[3] / 2;

    k_gauss<<<1, 128>>>(sigma);
    k_blur<<<3 * RANKS, 256>>>(rank1, 0);
    k_blur<<<3 * RANKS, 256>>>(rank2, 1);

    dim3 tgrid(IMG_W / 32, RANKS / 32, 3);
    k_split_t<<<tgrid, dim3(32, 8)>>>(0);
    k_split_t<<<tgrid, dim3(32, 8)>>>(1);

    cudaFuncSetAttribute(k_mma_gemm, cudaFuncAttributeMaxDynamicSharedMemorySize, SM_TOTAL);
    dim3 ggrid(IMG_W / 64, IMG_H / 128, 3);
    k_mma_gemm<<<ggrid, 256, SM_TOTAL>>>();

    k_sample<<<(npts + 255) / 256, 256>>>(coord, out, npts);
    (void)n_in; (void)out_size;
}

// round 5
// speedup vs baseline: 1.8839x; 1.2769x over previous
#include <cuda_runtime.h>
#include <cuda_bf16.h>
#include <math.h>
#include <stdint.h>

#define IMG_W 2048
#define IMG_H 2048
#define RANKS 128
#define KSZ   101
#define KHALF 50

// ---------------- scratch (__device__ globals; no allocation allowed) ----------------
__device__ float g_r1b[3 * RANKS * IMG_W];            // blurred rank1 fp32 [c][r][w]
__device__ float g_r2b[3 * RANKS * IMG_H];            // blurred rank2 fp32 [c][r][h]
// transposed bf16 hi/lo factors, K-contiguous: [c][x][r]
__device__ __nv_bfloat16 g_Bt_hi[3 * IMG_W * RANKS];  // from rank1 (w axis) -> GEMM B
__device__ __nv_bfloat16 g_Bt_lo[3 * IMG_W * RANKS];
__device__ __nv_bfloat16 g_At_hi[3 * IMG_H * RANKS];  // from rank2 (h axis) -> GEMM A
__device__ __nv_bfloat16 g_At_lo[3 * IMG_H * RANKS];
__device__ float g_img4[(size_t)IMG_H * IMG_W * 4];   // padded interleaved [h][w][4]

__device__ __forceinline__ uint32_t smem_u32(const void* p) {
    uint32_t a;
    asm("{ .reg .u64 t; cvta.to.shared.u64 t, %1; cvt.u32.u64 %0, t; }" : "=r"(a) : "l"(p));
    return a;
}

// =====================================================================
// K1: 1D blur (SAME, zero pad), both inputs in one launch.
// Block = one row. 4 consecutive outputs/thread, float4 sliding window.
// Gaussian weights computed per block from device sigma.
// =====================================================================
#define PAD    54                      // left pad; data at srow[54 .. 54+2048)
#define SROWSZ 2160                    // 54 + 2048 + 58 (multiple of 16B)
#define KWPAD  104                     // weights padded with zeros to 104

__global__ __launch_bounds__(256) void k_blur2(const float* __restrict__ rank1,
                                               const float* __restrict__ rank2,
                                               const float* __restrict__ sigma_p) {
    __shared__ __align__(16) float srow[SROWSZ];
    __shared__ __align__(16) float skw[KWPAD];
    const int which = blockIdx.x >= 3 * RANKS;
    const int row   = blockIdx.x - which * 3 * RANKS;
    const float* in  = (which ? rank2 : rank1) + (size_t)row * IMG_W;
    float*       out = (which ? g_r2b : g_r1b) + (size_t)row * IMG_W;
    const int tid = threadIdx.x;

    // weights (zero-padded tail)
    {
        float sigma = *sigma_p;
        float s   = fmaxf(sigma, 0.01f);
        float amp = 1.0f / fmaxf(sigma * 2.50662827463100050242f, 1.0f);
        for (int i = tid; i < KWPAD; i += 256) {
            float v = 0.0f;
            if (i < KSZ) {
                float n = (float)(i - KHALF);
                float t = n / s;
                v = amp * expf(-0.5f * t * t);
            }
            skw[i] = v;
        }
    }
    // padded row
    for (int i = tid; i < SROWSZ; i += 256) {
        int j = i - PAD;
        srow[i] = (j >= 0 && j < IMG_W) ? in[j] : 0.0f;
    }
    __syncthreads();

    #pragma unroll
    for (int grp = 0; grp < 2; grp++) {
        const int w0 = (tid + grp * 256) * 4;      // 0..2044, multiple of 4
        // output j (=0..3), tap kk (=0..100): image idx = w0+j+kk-50
        // -> srow[PAD + w0 + j + kk - 50] = srow[(w0+4) + kk + j]
        const float4* sv = (const float4*)&srow[w0 + 4];
        float a0 = 0.f, a1 = 0.f, a2 = 0.f, a3 = 0.f;
        float4 q0 = sv[0];
        #pragma unroll
        for (int t = 0; t < 26; t++) {             // kk = 4t .. 4t+3 (weights 101..103 are 0)
            float4 q1 = sv[t + 1];
            float4 kq = *(const float4*)&skw[4 * t];
            a0 = fmaf(kq.x, q0.x, a0); a1 = fmaf(kq.x, q0.y, a1);
            a2 = fmaf(kq.x, q0.z, a2); a3 = fmaf(kq.x, q0.w, a3);
            a0 = fmaf(kq.y, q0.y, a0); a1 = fmaf(kq.y, q0.z, a1);
            a2 = fmaf(kq.y, q0.w, a2); a3 = fmaf(kq.y, q1.x, a3);
            a0 = fmaf(kq.z, q0.z, a0); a1 = fmaf(kq.z, q0.w, a1);
            a2 = fmaf(kq.z, q1.x, a2); a3 = fmaf(kq.z, q1.y, a3);
            a0 = fmaf(kq.w, q0.w, a0); a1 = fmaf(kq.w, q1.x, a1);
            a2 = fmaf(kq.w, q1.y, a2); a3 = fmaf(kq.w, q1.z, a3);
            q0 = q1;
        }
        float4 res = make_float4(a0, a1, a2, a3);
        *(float4*)&out[w0] = res;
    }
}

// =====================================================================
// K2: transpose + bf16 hi/lo split. [c][r][x] fp32 -> [c][x][r] bf16 hi/lo
// grid.z = 6: z%3 = channel, z/3 = which
// =====================================================================
__global__ __launch_bounds__(256) void k_split_t() {
    __shared__ float t[32][33];
    const int c     = blockIdx.z % 3;
    const int which = blockIdx.z / 3;
    const int x0 = blockIdx.x * 32;
    const int r0 = blockIdx.y * 32;
    const float* src = (which ? g_r2b : g_r1b) + (size_t)c * RANKS * IMG_W;
    __nv_bfloat16* dhi = (which ? g_At_hi : g_Bt_hi) + (size_t)c * IMG_W * RANKS;
    __nv_bfloat16* dlo = (which ? g_At_lo : g_Bt_lo) + (size_t)c * IMG_W * RANKS;

    const int tx = threadIdx.x;        // 0..31
    const int ty = threadIdx.y;        // 0..7
    #pragma unroll
    for (int i = 0; i < 32; i += 8)
        t[ty + i][tx] = src[(size_t)(r0 + ty + i) * IMG_W + (x0 + tx)];
    __syncthreads();
    #pragma unroll
    for (int i = 0; i < 32; i += 8) {
        float v = t[tx][ty + i];                    // (r = r0+tx, x = x0+ty+i)
        __nv_bfloat16 hi = __float2bfloat16(v);
        float rem = v - __bfloat162float(hi);
        __nv_bfloat16 lo = __float2bfloat16(rem);
        size_t o = (size_t)(x0 + ty + i) * RANKS + (r0 + tx);
        dhi[o] = hi;
        dlo[o] = lo;
    }
}

// =====================================================================
// K3: mma.sync bf16 GEMM (hi/lo split, fp32 accum).
// Block 128(M=h) x 64(N=w), K=128 resident. 8 warps as 4(m) x 2(n).
// Per k-step: load ah,bh -> 8 mma; bl -> 8 mma; al -> 8 mma.
// =====================================================================
#define KP 136                      // padded smem stride in bf16 (272B)
#define SA_HI 0
#define SA_LO 34816
#define SB_HI 69632
#define SB_LO 87040
#define SM_TOTAL 104448

__device__ __forceinline__ void ldm_x4(uint32_t* r, uint32_t addr) {
    asm volatile("ldmatrix.sync.aligned.m8n8.x4.shared.b16 {%0,%1,%2,%3}, [%4];"
                 : "=r"(r[0]), "=r"(r[1]), "=r"(r[2]), "=r"(r[3]) : "r"(addr));
}
__device__ __forceinline__ void mma_bf16(float* d, const uint32_t* a, uint32_t b0, uint32_t b1) {
    asm volatile(
        "mma.sync.aligned.m16n8k16.row.col.f32.bf16.bf16.f32 "
        "{%0,%1,%2,%3}, {%4,%5,%6,%7}, {%8,%9}, {%0,%1,%2,%3};"
        : "+f"(d[0]), "+f"(d[1]), "+f"(d[2]), "+f"(d[3])
        : "r"(a[0]), "r"(a[1]), "r"(a[2]), "r"(a[3]), "r"(b0), "r"(b1));
}

__global__ __launch_bounds__(256, 2) void k_mma_gemm() {
    extern __shared__ char smem[];
    const uint32_t sb = smem_u32(smem);
    const int tid  = threadIdx.x;
    const int wid  = tid >> 5;
    const int lane = tid & 31;
    const int mw = wid & 3;          // 4 m-warps (32 rows each)
    const int nw = wid >> 2;         // 2 n-warps (32 cols each)
    const int c  = blockIdx.z;
    const int n0 = blockIdx.x * 64;
    const int m0 = blockIdx.y * 128;

    // ---- load tiles into padded smem (16B chunks) ----
    {
        const uint4* srcAh = (const uint4*)(g_At_hi + ((size_t)(c * IMG_H + m0)) * RANKS);
        const uint4* srcAl = (const uint4*)(g_At_lo + ((size_t)(c * IMG_H + m0)) * RANKS);
        const uint4* srcBh = (const uint4*)(g_Bt_hi + ((size_t)(c * IMG_W + n0)) * RANKS);
        const uint4* srcBl = (const uint4*)(g_Bt_lo + ((size_t)(c * IMG_W + n0)) * RANKS);
        #pragma unroll
        for (int it = 0; it < 8; it++) {           // A: 128 rows * 16 chunks
            int idx = tid + it * 256;
            int row = idx >> 4, ch = idx & 15;
            uint32_t off = (uint32_t)row * (KP * 2) + ch * 16;
            *(uint4*)(smem + SA_HI + off) = srcAh[(size_t)row * 16 + ch];
            *(uint4*)(smem + SA_LO + off) = srcAl[(size_t)row * 16 + ch];
        }
        #pragma unroll
        for (int it = 0; it < 4; it++) {           // B: 64 rows * 16 chunks
            int idx = tid + it * 256;
            int row = idx >> 4, ch = idx & 15;
            uint32_t off = (uint32_t)row * (KP * 2) + ch * 16;
            *(uint4*)(smem + SB_HI + off) = srcBh[(size_t)row * 16 + ch];
            *(uint4*)(smem + SB_LO + off) = srcBl[(size_t)row * 16 + ch];
        }
    }
    __syncthreads();

    float d[2][4][4];
    #pragma unroll
    for (int i = 0; i < 2; i++)
        #pragma unroll
        for (int j = 0; j < 4; j++)
            #pragma unroll
            for (int r = 0; r < 4; r++) d[i][j][r] = 0.0f;

    const int a_row = (lane & 15);
    const int a_ko  = (lane >> 4) * 8;
    const int quad  = lane >> 3;
    const int b_row = ((quad >> 1) * 8) + (lane & 7);
    const int b_ko  = (quad & 1) * 8;

    #pragma unroll
    for (int ks = 0; ks < 8; ks++) {
        const int k0 = ks * 16;
        const uint32_t aoff = ((uint32_t)(mw * 32 + a_row) * KP + k0 + a_ko) * 2;
        const uint32_t boff = ((uint32_t)(nw * 32 + b_row) * KP + k0 + b_ko) * 2;
        uint32_t ah[2][4], al[2][4], bh[2][4], bl[2][4];

        ldm_x4(ah[0], sb + SA_HI + aoff);
        ldm_x4(ah[1], sb + SA_HI + aoff + 16 * KP * 2);
        ldm_x4(bh[0], sb + SB_HI + boff);
        ldm_x4(bh[1], sb + SB_HI + boff + 16 * KP * 2);
        #pragma unroll
        for (int mt = 0; mt < 2; mt++)
            #pragma unroll
            for (int nt = 0; nt < 4; nt++)
                mma_bf16(d[mt][nt], ah[mt], bh[nt >> 1][(nt & 1) * 2],
                         bh[nt >> 1][(nt & 1) * 2 + 1]);

        ldm_x4(bl[0], sb + SB_LO + boff);
        ldm_x4(bl[1], sb + SB_LO + boff + 16 * KP * 2);
        #pragma unroll
        for (int mt = 0; mt < 2; mt++)
            #pragma unroll
            for (int nt = 0; nt < 4; nt++)
                mma_bf16(d[mt][nt], ah[mt], bl[nt >> 1][(nt & 1) * 2],
                         bl[nt >> 1][(nt & 1) * 2 + 1]);

        ldm_x4(al[0], sb + SA_LO + aoff);
        ldm_x4(al[1], sb + SA_LO + aoff + 16 * KP * 2);
        #pragma unroll
        for (int mt = 0; mt < 2; mt++)
            #pragma unroll
            for (int nt = 0; nt < 4; nt++)
                mma_bf16(d[mt][nt], al[mt], bh[nt >> 1][(nt & 1) * 2],
                         bh[nt >> 1][(nt & 1) * 2 + 1]);
    }

    // ---- epilogue: write channel-interleaved image ----
    const int g = lane >> 2;
    const int t = lane & 3;
    #pragma unroll
    for (int mt = 0; mt < 2; mt++) {
        #pragma unroll
        for (int nt = 0; nt < 4; nt++) {
            int m = m0 + mw * 32 + mt * 16 + g;
            int n = n0 + nw * 32 + nt * 8 + t * 2;
            float* p0 = g_img4 + ((size_t)m * IMG_W + n) * 4 + c;
            p0[0] = d[mt][nt][0];
            p0[4] = d[mt][nt][1];
            float* p1 = g_img4 + ((size_t)(m + 8) * IMG_W + n) * 4 + c;
            p1[0] = d[mt][nt][2];
            p1[4] = d[mt][nt][3];
        }
    }
}

// =====================================================================
// K4: bilinear grid sample; float4 taps from padded image
// =====================================================================
__global__ __launch_bounds__(256) void k_sample(const float* __restrict__ coord,
                                                float* __restrict__ out, int npts) {
    int p = blockIdx.x * blockDim.x + threadIdx.x;
    if (p >= npts) return;

    float2 gxy = reinterpret_cast<const float2*>(coord)[p];
    float x = (gxy.x + 1.0f) * (IMG_W * 0.5f) - 0.5f;
    float y = (gxy.y + 1.0f) * (IMG_H * 0.5f) - 0.5f;
    float x0f = floorf(x), y0f = floorf(y);
    float wx1 = x - x0f, wy1 = y - y0f;
    float wx0 = 1.0f - wx1, wy0 = 1.0f - wy1;

    int x0 = (int)x0f, y0 = (int)y0f;
    int x1 = x0 + 1,  y1 = y0 + 1;

    float vx0 = (x0 >= 0 && x0 < IMG_W) ? 1.0f : 0.0f;
    float vx1 = (x1 >= 0 && x1 < IMG_W) ? 1.0f : 0.0f;
    float vy0 = (y0 >= 0 && y0 < IMG_H) ? 1.0f : 0.0f;
    float vy1 = (y1 >= 0 && y1 < IMG_H) ? 1.0f : 0.0f;

    int cx0 = min(max(x0, 0), IMG_W - 1);
    int cx1 = min(max(x1, 0), IMG_W - 1);
    int cy0 = min(max(y0, 0), IMG_H - 1);
    int cy1 = min(max(y1, 0), IMG_H - 1);

    float w00 = wx0 * vx0 * wy0 * vy0;
    float w10 = wx1 * vx1 * wy0 * vy0;
    float w01 = wx0 * vx0 * wy1 * vy1;
    float w11 = wx1 * vx1 * wy1 * vy1;

    const float4* img = (const float4*)g_img4;
    float4 v00 = __ldg(&img[(size_t)cy0 * IMG_W + cx0]);
    float4 v10 = __ldg(&img[(size_t)cy0 * IMG_W + cx1]);
    float4 v01 = __ldg(&img[(size_t)cy1 * IMG_W + cx0]);
    float4 v11 = __ldg(&img[(size_t)cy1 * IMG_W + cx1]);

    out[(size_t)p * 3 + 0] = w00 * v00.x + w10 * v10.x + w01 * v01.x + w11 * v11.x;
    out[(size_t)p * 3 + 1] = w00 * v00.y + w10 * v10.y + w01 * v01.y + w11 * v11.y;
    out[(size_t)p * 3 + 2] = w00 * v00.z + w10 * v10.z + w01 * v01.z + w11 * v11.z;
}

// =====================================================================
extern "C" void kernel_launch(void* const* d_in, const int* in_sizes, int n_in,
                              void* d_out, int out_size) {
    const float* rank1 = (const float*)d_in[0];
    const float* rank2 = (const float*)d_in[1];
    const float* sigma = (const float*)d_in[2];
    const float* coord = (const float*)d_in[3];
    float* out = (float*)d_out;

    const int npts = in_sizes[3] / 2;

    k_blur2<<<6 * RANKS, 256>>>(rank1, rank2, sigma);

    dim3 tgrid(IMG_W / 32, RANKS / 32, 6);
    k_split_t<<<tgrid, dim3(32, 8)>>>();

    cudaFuncSetAttribute(k_mma_gemm, cudaFuncAttributeMaxDynamicSharedMemorySize, SM_TOTAL);
    dim3 ggrid(IMG_W / 64, IMG_H / 128, 3);
    k_mma_gemm<<<ggrid, 256, SM_TOTAL>>>();

    k_sample<<<(npts + 255) / 256, 256>>>(coord, out, npts);
    (void)n_in; (void)out_size;
}

// round 6
// speedup vs baseline: 2.0049x; 1.0642x over previous
#include <cuda_runtime.h>
#include <cuda_bf16.h>
#include <cuda_fp16.h>
#include <math.h>
#include <stdint.h>

#define IMG_W 2048
#define IMG_H 2048
#define RANKS 128
#define KSZ   101
#define KHALF 50

// ---------------- scratch (__device__ globals; no allocation allowed) ----------------
__device__ float g_r1b[3 * RANKS * IMG_W];            // blurred rank1 fp32 [c][r][w]
__device__ float g_r2b[3 * RANKS * IMG_H];            // blurred rank2 fp32 [c][r][h]
// transposed bf16 hi/lo factors, K-contiguous: [c][x][r]
__device__ __nv_bfloat16 g_Bt_hi[3 * IMG_W * RANKS];  // from rank1 (w axis) -> GEMM B
__device__ __nv_bfloat16 g_Bt_lo[3 * IMG_W * RANKS];
__device__ __nv_bfloat16 g_At_hi[3 * IMG_H * RANKS];  // from rank2 (h axis) -> GEMM A
__device__ __nv_bfloat16 g_At_lo[3 * IMG_H * RANKS];
__device__ __half g_imgh[(size_t)IMG_H * IMG_W * 4];  // fp16 interleaved [h][w][4], 32MB

__device__ __forceinline__ uint32_t smem_u32(const void* p) {
    uint32_t a;
    asm("{ .reg .u64 t; cvta.to.shared.u64 t, %1; cvt.u32.u64 %0, t; }" : "=r"(a) : "l"(p));
    return a;
}

// =====================================================================
// K1: 1D blur (SAME, zero pad), both inputs in one launch.
// =====================================================================
#define PAD    54
#define SROWSZ 2160
#define KWPAD  104

__global__ __launch_bounds__(256) void k_blur2(const float* __restrict__ rank1,
                                               const float* __restrict__ rank2,
                                               const float* __restrict__ sigma_p) {
    __shared__ __align__(16) float srow[SROWSZ];
    __shared__ __align__(16) float skw[KWPAD];
    const int which = blockIdx.x >= 3 * RANKS;
    const int row   = blockIdx.x - which * 3 * RANKS;
    const float* in  = (which ? rank2 : rank1) + (size_t)row * IMG_W;
    float*       out = (which ? g_r2b : g_r1b) + (size_t)row * IMG_W;
    const int tid = threadIdx.x;

    {
        float sigma = *sigma_p;
        float s   = fmaxf(sigma, 0.01f);
        float amp = 1.0f / fmaxf(sigma * 2.50662827463100050242f, 1.0f);
        for (int i = tid; i < KWPAD; i += 256) {
            float v = 0.0f;
            if (i < KSZ) {
                float n = (float)(i - KHALF);
                float t = n / s;
                v = amp * expf(-0.5f * t * t);
            }
            skw[i] = v;
        }
    }
    for (int i = tid; i < SROWSZ; i += 256) {
        int j = i - PAD;
        srow[i] = (j >= 0 && j < IMG_W) ? in[j] : 0.0f;
    }
    __syncthreads();

    #pragma unroll
    for (int grp = 0; grp < 2; grp++) {
        const int w0 = (tid + grp * 256) * 4;
        const float4* sv = (const float4*)&srow[w0 + 4];
        float a0 = 0.f, a1 = 0.f, a2 = 0.f, a3 = 0.f;
        float4 q0 = sv[0];
        #pragma unroll
        for (int t = 0; t < 26; t++) {
            float4 q1 = sv[t + 1];
            float4 kq = *(const float4*)&skw[4 * t];
            a0 = fmaf(kq.x, q0.x, a0); a1 = fmaf(kq.x, q0.y, a1);
            a2 = fmaf(kq.x, q0.z, a2); a3 = fmaf(kq.x, q0.w, a3);
            a0 = fmaf(kq.y, q0.y, a0); a1 = fmaf(kq.y, q0.z, a1);
            a2 = fmaf(kq.y, q0.w, a2); a3 = fmaf(kq.y, q1.x, a3);
            a0 = fmaf(kq.z, q0.z, a0); a1 = fmaf(kq.z, q0.w, a1);
            a2 = fmaf(kq.z, q1.x, a2); a3 = fmaf(kq.z, q1.y, a3);
            a0 = fmaf(kq.w, q0.w, a0); a1 = fmaf(kq.w, q1.x, a1);
            a2 = fmaf(kq.w, q1.y, a2); a3 = fmaf(kq.w, q1.z, a3);
            q0 = q1;
        }
        float4 res = make_float4(a0, a1, a2, a3);
        *(float4*)&out[w0] = res;
    }
}

// =====================================================================
// K2: transpose + bf16 hi/lo split. grid.z = 6: z%3 = channel, z/3 = which
// =====================================================================
__global__ __launch_bounds__(256) void k_split_t() {
    __shared__ float t[32][33];
    const int c     = blockIdx.z % 3;
    const int which = blockIdx.z / 3;
    const int x0 = blockIdx.x * 32;
    const int r0 = blockIdx.y * 32;
    const float* src = (which ? g_r2b : g_r1b) + (size_t)c * RANKS * IMG_W;
    __nv_bfloat16* dhi = (which ? g_At_hi : g_Bt_hi) + (size_t)c * IMG_W * RANKS;
    __nv_bfloat16* dlo = (which ? g_At_lo : g_Bt_lo) + (size_t)c * IMG_W * RANKS;

    const int tx = threadIdx.x;
    const int ty = threadIdx.y;
    #pragma unroll
    for (int i = 0; i < 32; i += 8)
        t[ty + i][tx] = src[(size_t)(r0 + ty + i) * IMG_W + (x0 + tx)];
    __syncthreads();
    #pragma unroll
    for (int i = 0; i < 32; i += 8) {
        float v = t[tx][ty + i];
        __nv_bfloat16 hi = __float2bfloat16(v);
        float rem = v - __bfloat162float(hi);
        __nv_bfloat16 lo = __float2bfloat16(rem);
        size_t o = (size_t)(x0 + ty + i) * RANKS + (r0 + tx);
        dhi[o] = hi;
        dlo[o] = lo;
    }
}

// =====================================================================
// K3: mma.sync bf16 GEMM (hi/lo split, fp32 accum). fp16 image epilogue.
// =====================================================================
#define KP 136
#define SA_HI 0
#define SA_LO 34816
#define SB_HI 69632
#define SB_LO 87040
#define SM_TOTAL 104448

__device__ __forceinline__ void ldm_x4(uint32_t* r, uint32_t addr) {
    asm volatile("ldmatrix.sync.aligned.m8n8.x4.shared.b16 {%0,%1,%2,%3}, [%4];"
                 : "=r"(r[0]), "=r"(r[1]), "=r"(r[2]), "=r"(r[3]) : "r"(addr));
}
__device__ __forceinline__ void mma_bf16(float* d, const uint32_t* a, uint32_t b0, uint32_t b1) {
    asm volatile(
        "mma.sync.aligned.m16n8k16.row.col.f32.bf16.bf16.f32 "
        "{%0,%1,%2,%3}, {%4,%5,%6,%7}, {%8,%9}, {%0,%1,%2,%3};"
        : "+f"(d[0]), "+f"(d[1]), "+f"(d[2]), "+f"(d[3])
        : "r"(a[0]), "r"(a[1]), "r"(a[2]), "r"(a[3]), "r"(b0), "r"(b1));
}

__global__ __launch_bounds__(256, 2) void k_mma_gemm() {
    extern __shared__ char smem[];
    const uint32_t sb = smem_u32(smem);
    const int tid  = threadIdx.x;
    const int wid  = tid >> 5;
    const int lane = tid & 31;
    const int mw = wid & 3;
    const int nw = wid >> 2;
    const int c  = blockIdx.z;
    const int n0 = blockIdx.x * 64;
    const int m0 = blockIdx.y * 128;

    {
        const uint4* srcAh = (const uint4*)(g_At_hi + ((size_t)(c * IMG_H + m0)) * RANKS);
        const uint4* srcAl = (const uint4*)(g_At_lo + ((size_t)(c * IMG_H + m0)) * RANKS);
        const uint4* srcBh = (const uint4*)(g_Bt_hi + ((size_t)(c * IMG_W + n0)) * RANKS);
        const uint4* srcBl = (const uint4*)(g_Bt_lo + ((size_t)(c * IMG_W + n0)) * RANKS);
        #pragma unroll
        for (int it = 0; it < 8; it++) {
            int idx = tid + it * 256;
            int row = idx >> 4, ch = idx & 15;
            uint32_t off = (uint32_t)row * (KP * 2) + ch * 16;
            *(uint4*)(smem + SA_HI + off) = srcAh[(size_t)row * 16 + ch];
            *(uint4*)(smem + SA_LO + off) = srcAl[(size_t)row * 16 + ch];
        }
        #pragma unroll
        for (int it = 0; it < 4; it++) {
            int idx = tid + it * 256;
            int row = idx >> 4, ch = idx & 15;
            uint32_t off = (uint32_t)row * (KP * 2) + ch * 16;
            *(uint4*)(smem + SB_HI + off) = srcBh[(size_t)row * 16 + ch];
            *(uint4*)(smem + SB_LO + off) = srcBl[(size_t)row * 16 + ch];
        }
    }
    __syncthreads();

    float d[2][4][4];
    #pragma unroll
    for (int i = 0; i < 2; i++)
        #pragma unroll
        for (int j = 0; j < 4; j++)
            #pragma unroll
            for (int r = 0; r < 4; r++) d[i][j][r] = 0.0f;

    const int a_row = (lane & 15);
    const int a_ko  = (lane >> 4) * 8;
    const int quad  = lane >> 3;
    const int b_row = ((quad >> 1) * 8) + (lane & 7);
    const int b_ko  = (quad & 1) * 8;

    #pragma unroll
    for (int ks = 0; ks < 8; ks++) {
        const int k0 = ks * 16;
        const uint32_t aoff = ((uint32_t)(mw * 32 + a_row) * KP + k0 + a_ko) * 2;
        const uint32_t boff = ((uint32_t)(nw * 32 + b_row) * KP + k0 + b_ko) * 2;
        uint32_t ah[2][4], al[2][4], bh[2][4], bl[2][4];

        ldm_x4(ah[0], sb + SA_HI + aoff);
        ldm_x4(ah[1], sb + SA_HI + aoff + 16 * KP * 2);
        ldm_x4(bh[0], sb + SB_HI + boff);
        ldm_x4(bh[1], sb + SB_HI + boff + 16 * KP * 2);
        #pragma unroll
        for (int mt = 0; mt < 2; mt++)
            #pragma unroll
            for (int nt = 0; nt < 4; nt++)
                mma_bf16(d[mt][nt], ah[mt], bh[nt >> 1][(nt & 1) * 2],
                         bh[nt >> 1][(nt & 1) * 2 + 1]);

        ldm_x4(bl[0], sb + SB_LO + boff);
        ldm_x4(bl[1], sb + SB_LO + boff + 16 * KP * 2);
        #pragma unroll
        for (int mt = 0; mt < 2; mt++)
            #pragma unroll
            for (int nt = 0; nt < 4; nt++)
                mma_bf16(d[mt][nt], ah[mt], bl[nt >> 1][(nt & 1) * 2],
                         bl[nt >> 1][(nt & 1) * 2 + 1]);

        ldm_x4(al[0], sb + SA_LO + aoff);
        ldm_x4(al[1], sb + SA_LO + aoff + 16 * KP * 2);
        #pragma unroll
        for (int mt = 0; mt < 2; mt++)
            #pragma unroll
            for (int nt = 0; nt < 4; nt++)
                mma_bf16(d[mt][nt], al[mt], bh[nt >> 1][(nt & 1) * 2],
                         bh[nt >> 1][(nt & 1) * 2 + 1]);
    }

    // ---- epilogue: write fp16 channel-interleaved image ----
    const int g = lane >> 2;
    const int t = lane & 3;
    #pragma unroll
    for (int mt = 0; mt < 2; mt++) {
        #pragma unroll
        for (int nt = 0; nt < 4; nt++) {
            int m = m0 + mw * 32 + mt * 16 + g;
            int n = n0 + nw * 32 + nt * 8 + t * 2;
            __half* p0 = g_imgh + ((size_t)m * IMG_W + n) * 4 + c;
            p0[0] = __float2half_rn(d[mt][nt][0]);
            p0[4] = __float2half_rn(d[mt][nt][1]);
            __half* p1 = g_imgh + ((size_t)(m + 8) * IMG_W + n) * 4 + c;
            p1[0] = __float2half_rn(d[mt][nt][2]);
            p1[4] = __float2half_rn(d[mt][nt][3]);
        }
    }
}

// =====================================================================
// K4: bilinear grid sample from fp16 image (8B pixels)
// =====================================================================
__global__ __launch_bounds__(256) void k_sample(const float* __restrict__ coord,
                                                float* __restrict__ out, int npts) {
    int p = blockIdx.x * blockDim.x + threadIdx.x;
    if (p >= npts) return;

    float2 gxy = reinterpret_cast<const float2*>(coord)[p];
    float x = (gxy.x + 1.0f) * (IMG_W * 0.5f) - 0.5f;
    float y = (gxy.y + 1.0f) * (IMG_H * 0.5f) - 0.5f;
    float x0f = floorf(x), y0f = floorf(y);
    float wx1 = x - x0f, wy1 = y - y0f;
    float wx0 = 1.0f - wx1, wy0 = 1.0f - wy1;

    int x0 = (int)x0f, y0 = (int)y0f;
    int x1 = x0 + 1,  y1 = y0 + 1;

    float vx0 = (x0 >= 0 && x0 < IMG_W) ? 1.0f : 0.0f;
    float vx1 = (x1 >= 0 && x1 < IMG_W) ? 1.0f : 0.0f;
    float vy0 = (y0 >= 0 && y0 < IMG_H) ? 1.0f : 0.0f;
    float vy1 = (y1 >= 0 && y1 < IMG_H) ? 1.0f : 0.0f;

    int cx0 = min(max(x0, 0), IMG_W - 1);
    int cx1 = min(max(x1, 0), IMG_W - 1);
    int cy0 = min(max(y0, 0), IMG_H - 1);
    int cy1 = min(max(y1, 0), IMG_H - 1);

    float w00 = wx0 * vx0 * wy0 * vy0;
    float w10 = wx1 * vx1 * wy0 * vy0;
    float w01 = wx0 * vx0 * wy1 * vy1;
    float w11 = wx1 * vx1 * wy1 * vy1;

    const __half2* img = (const __half2*)g_imgh;   // pixel = 2 x half2
    size_t i00 = ((size_t)cy0 * IMG_W + cx0) * 2;
    size_t i10 = ((size_t)cy0 * IMG_W + cx1) * 2;
    size_t i01 = ((size_t)cy1 * IMG_W + cx0) * 2;
    size_t i11 = ((size_t)cy1 * IMG_W + cx1) * 2;

    float2 a00 = __half22float2(__ldg(&img[i00]));
    float2 b00 = __half22float2(__ldg(&img[i00 + 1]));
    float2 a10 = __half22float2(__ldg(&img[i10]));
    float2 b10 = __half22float2(__ldg(&img[i10 + 1]));
    float2 a01 = __half22float2(__ldg(&img[i01]));
    float2 b01 = __half22float2(__ldg(&img[i01 + 1]));
    float2 a11 = __half22float2(__ldg(&img[i11]));
    float2 b11 = __half22float2(__ldg(&img[i11 + 1]));

    out[(size_t)p * 3 + 0] = w00 * a00.x + w10 * a10.x + w01 * a01.x + w11 * a11.x;
    out[(size_t)p * 3 + 1] = w00 * a00.y + w10 * a10.y + w01 * a01.y + w11 * a11.y;
    out[(size_t)p * 3 + 2] = w00 * b00.x + w10 * b10.x + w01 * b01.x + w11 * b11.x;
}

// =====================================================================
extern "C" void kernel_launch(void* const* d_in, const int* in_sizes, int n_in,
                              void* d_out, int out_size) {
    const float* rank1 = (const float*)d_in[0];
    const float* rank2 = (const float*)d_in[1];
    const float* sigma = (const float*)d_in[2];
    const float* coord = (const float*)d_in[3];
    float* out = (float*)d_out;

    const int npts = in_sizes[3] / 2;

    k_blur2<<<6 * RANKS, 256>>>(rank1, rank2, sigma);

    dim3 tgrid(IMG_W / 32, RANKS / 32, 6);
    k_split_t<<<tgrid, dim3(32, 8)>>>();

    cudaFuncSetAttribute(k_mma_gemm, cudaFuncAttributeMaxDynamicSharedMemorySize, SM_TOTAL);
    dim3 ggrid(IMG_W / 64, IMG_H / 128, 3);
    k_mma_gemm<<<ggrid, 256, SM_TOTAL>>>();

    k_sample<<<(npts + 255) / 256, 256>>>(coord, out, npts);
    (void)n_in; (void)out_size;
}

// round 7
// speedup vs baseline: 2.1118x; 1.0533x over previous
#include <cuda_runtime.h>
#include <cuda_bf16.h>
#include <cuda_fp16.h>
#include <math.h>
#include <stdint.h>

#define IMG_W 2048
#define IMG_H 2048
#define RANKS 128
#define KSZ   101
#define KHALF 50

// ---------------- scratch (__device__ globals; no allocation allowed) ----------------
__device__ float g_r1b[3 * RANKS * IMG_W];            // blurred rank1 fp32 [c][r][w]
__device__ float g_r2b[3 * RANKS * IMG_H];            // blurred rank2 fp32 [c][r][h]
// transposed bf16 hi/lo factors, K-contiguous: [c][x][r]
__device__ __nv_bfloat16 g_Bt_hi[3 * IMG_W * RANKS];  // from rank1 (w axis) -> GEMM B
__device__ __nv_bfloat16 g_Bt_lo[3 * IMG_W * RANKS];
__device__ __nv_bfloat16 g_At_hi[3 * IMG_H * RANKS];  // from rank2 (h axis) -> GEMM A
__device__ __nv_bfloat16 g_At_lo[3 * IMG_H * RANKS];
__device__ __half g_imgh[(size_t)IMG_H * IMG_W * 4];  // fp16 interleaved [h][w][4], 32MB

__device__ __forceinline__ uint32_t smem_u32(const void* p) {
    uint32_t a;
    asm("{ .reg .u64 t; cvta.to.shared.u64 t, %1; cvt.u32.u64 %0, t; }" : "=r"(a) : "l"(p));
    return a;
}

// =====================================================================
// K1: 1D blur (SAME, zero pad), both inputs in one launch.
// =====================================================================
#define PAD    54
#define SROWSZ 2160
#define KWPAD  104

__global__ __launch_bounds__(256) void k_blur2(const float* __restrict__ rank1,
                                               const float* __restrict__ rank2,
                                               const float* __restrict__ sigma_p) {
    __shared__ __align__(16) float srow[SROWSZ];
    __shared__ __align__(16) float skw[KWPAD];
    const int which = blockIdx.x >= 3 * RANKS;
    const int row   = blockIdx.x - which * 3 * RANKS;
    const float* in  = (which ? rank2 : rank1) + (size_t)row * IMG_W;
    float*       out = (which ? g_r2b : g_r1b) + (size_t)row * IMG_W;
    const int tid = threadIdx.x;

    {
        float sigma = *sigma_p;
        float s   = fmaxf(sigma, 0.01f);
        float amp = 1.0f / fmaxf(sigma * 2.50662827463100050242f, 1.0f);
        for (int i = tid; i < KWPAD; i += 256) {
            float v = 0.0f;
            if (i < KSZ) {
                float n = (float)(i - KHALF);
                float t = n / s;
                v = amp * expf(-0.5f * t * t);
            }
            skw[i] = v;
        }
    }
    for (int i = tid; i < SROWSZ; i += 256) {
        int j = i - PAD;
        srow[i] = (j >= 0 && j < IMG_W) ? in[j] : 0.0f;
    }
    __syncthreads();

    #pragma unroll
    for (int grp = 0; grp < 2; grp++) {
        const int w0 = (tid + grp * 256) * 4;
        const float4* sv = (const float4*)&srow[w0 + 4];
        float a0 = 0.f, a1 = 0.f, a2 = 0.f, a3 = 0.f;
        float4 q0 = sv[0];
        #pragma unroll
        for (int t = 0; t < 26; t++) {
            float4 q1 = sv[t + 1];
            float4 kq = *(const float4*)&skw[4 * t];
            a0 = fmaf(kq.x, q0.x, a0); a1 = fmaf(kq.x, q0.y, a1);
            a2 = fmaf(kq.x, q0.z, a2); a3 = fmaf(kq.x, q0.w, a3);
            a0 = fmaf(kq.y, q0.y, a0); a1 = fmaf(kq.y, q0.z, a1);
            a2 = fmaf(kq.y, q0.w, a2); a3 = fmaf(kq.y, q1.x, a3);
            a0 = fmaf(kq.z, q0.z, a0); a1 = fmaf(kq.z, q0.w, a1);
            a2 = fmaf(kq.z, q1.x, a2); a3 = fmaf(kq.z, q1.y, a3);
            a0 = fmaf(kq.w, q0.w, a0); a1 = fmaf(kq.w, q1.x, a1);
            a2 = fmaf(kq.w, q1.y, a2); a3 = fmaf(kq.w, q1.z, a3);
            q0 = q1;
        }
        float4 res = make_float4(a0, a1, a2, a3);
        *(float4*)&out[w0] = res;
    }
}

// =====================================================================
// K2: transpose + bf16 hi/lo split. grid.z = 6: z%3 = channel, z/3 = which
// =====================================================================
__global__ __launch_bounds__(256) void k_split_t() {
    __shared__ float t[32][33];
    const int c     = blockIdx.z % 3;
    const int which = blockIdx.z / 3;
    const int x0 = blockIdx.x * 32;
    const int r0 = blockIdx.y * 32;
    const float* src = (which ? g_r2b : g_r1b) + (size_t)c * RANKS * IMG_W;
    __nv_bfloat16* dhi = (which ? g_At_hi : g_Bt_hi) + (size_t)c * IMG_W * RANKS;
    __nv_bfloat16* dlo = (which ? g_At_lo : g_Bt_lo) + (size_t)c * IMG_W * RANKS;

    const int tx = threadIdx.x;
    const int ty = threadIdx.y;
    #pragma unroll
    for (int i = 0; i < 32; i += 8)
        t[ty + i][tx] = src[(size_t)(r0 + ty + i) * IMG_W + (x0 + tx)];
    __syncthreads();
    #pragma unroll
    for (int i = 0; i < 32; i += 8) {
        float v = t[tx][ty + i];
        __nv_bfloat16 hi = __float2bfloat16(v);
        float rem = v - __bfloat162float(hi);
        __nv_bfloat16 lo = __float2bfloat16(rem);
        size_t o = (size_t)(x0 + ty + i) * RANKS + (r0 + tx);
        dhi[o] = hi;
        dlo[o] = lo;
    }
}

// =====================================================================
// K3: mma.sync bf16 GEMM (hi/lo split, fp32 accum). fp16 image epilogue.
// =====================================================================
#define KP 136
#define SA_HI 0
#define SA_LO 34816
#define SB_HI 69632
#define SB_LO 87040
#define SM_TOTAL 104448

__device__ __forceinline__ void ldm_x4(uint32_t* r, uint32_t addr) {
    asm volatile("ldmatrix.sync.aligned.m8n8.x4.shared.b16 {%0,%1,%2,%3}, [%4];"
                 : "=r"(r[0]), "=r"(r[1]), "=r"(r[2]), "=r"(r[3]) : "r"(addr));
}
__device__ __forceinline__ void mma_bf16(float* d, const uint32_t* a, uint32_t b0, uint32_t b1) {
    asm volatile(
        "mma.sync.aligned.m16n8k16.row.col.f32.bf16.bf16.f32 "
        "{%0,%1,%2,%3}, {%4,%5,%6,%7}, {%8,%9}, {%0,%1,%2,%3};"
        : "+f"(d[0]), "+f"(d[1]), "+f"(d[2]), "+f"(d[3])
        : "r"(a[0]), "r"(a[1]), "r"(a[2]), "r"(a[3]), "r"(b0), "r"(b1));
}

__global__ __launch_bounds__(256, 2) void k_mma_gemm() {
    extern __shared__ char smem[];
    const uint32_t sb = smem_u32(smem);
    const int tid  = threadIdx.x;
    const int wid  = tid >> 5;
    const int lane = tid & 31;
    const int mw = wid & 3;
    const int nw = wid >> 2;
    const int c  = blockIdx.z;
    const int n0 = blockIdx.x * 64;
    const int m0 = blockIdx.y * 128;

    {
        const uint4* srcAh = (const uint4*)(g_At_hi + ((size_t)(c * IMG_H + m0)) * RANKS);
        const uint4* srcAl = (const uint4*)(g_At_lo + ((size_t)(c * IMG_H + m0)) * RANKS);
        const uint4* srcBh = (const uint4*)(g_Bt_hi + ((size_t)(c * IMG_W + n0)) * RANKS);
        const uint4* srcBl = (const uint4*)(g_Bt_lo + ((size_t)(c * IMG_W + n0)) * RANKS);
        #pragma unroll
        for (int it = 0; it < 8; it++) {
            int idx = tid + it * 256;
            int row = idx >> 4, ch = idx & 15;
            uint32_t off = (uint32_t)row * (KP * 2) + ch * 16;
            *(uint4*)(smem + SA_HI + off) = srcAh[(size_t)row * 16 + ch];
            *(uint4*)(smem + SA_LO + off) = srcAl[(size_t)row * 16 + ch];
        }
        #pragma unroll
        for (int it = 0; it < 4; it++) {
            int idx = tid + it * 256;
            int row = idx >> 4, ch = idx & 15;
            uint32_t off = (uint32_t)row * (KP * 2) + ch * 16;
            *(uint4*)(smem + SB_HI + off) = srcBh[(size_t)row * 16 + ch];
            *(uint4*)(smem + SB_LO + off) = srcBl[(size_t)row * 16 + ch];
        }
    }
    __syncthreads();

    float d[2][4][4];
    #pragma unroll
    for (int i = 0; i < 2; i++)
        #pragma unroll
        for (int j = 0; j < 4; j++)
            #pragma unroll
            for (int r = 0; r < 4; r++) d[i][j][r] = 0.0f;

    const int a_row = (lane & 15);
    const int a_ko  = (lane >> 4) * 8;
    const int quad  = lane >> 3;
    const int b_row = ((quad >> 1) * 8) + (lane & 7);
    const int b_ko  = (quad & 1) * 8;

    #pragma unroll
    for (int ks = 0; ks < 8; ks++) {
        const int k0 = ks * 16;
        const uint32_t aoff = ((uint32_t)(mw * 32 + a_row) * KP + k0 + a_ko) * 2;
        const uint32_t boff = ((uint32_t)(nw * 32 + b_row) * KP + k0 + b_ko) * 2;
        uint32_t ah[2][4], al[2][4], bh[2][4], bl[2][4];

        ldm_x4(ah[0], sb + SA_HI + aoff);
        ldm_x4(ah[1], sb + SA_HI + aoff + 16 * KP * 2);
        ldm_x4(bh[0], sb + SB_HI + boff);
        ldm_x4(bh[1], sb + SB_HI + boff + 16 * KP * 2);
        #pragma unroll
        for (int mt = 0; mt < 2; mt++)
            #pragma unroll
            for (int nt = 0; nt < 4; nt++)
                mma_bf16(d[mt][nt], ah[mt], bh[nt >> 1][(nt & 1) * 2],
                         bh[nt >> 1][(nt & 1) * 2 + 1]);

        ldm_x4(bl[0], sb + SB_LO + boff);
        ldm_x4(bl[1], sb + SB_LO + boff + 16 * KP * 2);
        #pragma unroll
        for (int mt = 0; mt < 2; mt++)
            #pragma unroll
            for (int nt = 0; nt < 4; nt++)
                mma_bf16(d[mt][nt], ah[mt], bl[nt >> 1][(nt & 1) * 2],
                         bl[nt >> 1][(nt & 1) * 2 + 1]);

        ldm_x4(al[0], sb + SA_LO + aoff);
        ldm_x4(al[1], sb + SA_LO + aoff + 16 * KP * 2);
        #pragma unroll
        for (int mt = 0; mt < 2; mt++)
            #pragma unroll
            for (int nt = 0; nt < 4; nt++)
                mma_bf16(d[mt][nt], al[mt], bh[nt >> 1][(nt & 1) * 2],
                         bh[nt >> 1][(nt & 1) * 2 + 1]);
    }

    // ---- epilogue: write fp16 channel-interleaved image ----
    const int g = lane >> 2;
    const int t = lane & 3;
    #pragma unroll
    for (int mt = 0; mt < 2; mt++) {
        #pragma unroll
        for (int nt = 0; nt < 4; nt++) {
            int m = m0 + mw * 32 + mt * 16 + g;
            int n = n0 + nw * 32 + nt * 8 + t * 2;
            __half* p0 = g_imgh + ((size_t)m * IMG_W + n) * 4 + c;
            p0[0] = __float2half_rn(d[mt][nt][0]);
            p0[4] = __float2half_rn(d[mt][nt][1]);
            __half* p1 = g_imgh + ((size_t)(m + 8) * IMG_W + n) * 4 + c;
            p1[0] = __float2half_rn(d[mt][nt][2]);
            p1[4] = __float2half_rn(d[mt][nt][3]);
        }
    }
}

// =====================================================================
// K4: bilinear grid sample; ONE 8B load per tap (pixel = 4 x fp16)
// =====================================================================
__global__ __launch_bounds__(256) void k_sample(const float* __restrict__ coord,
                                                float* __restrict__ out, int npts) {
    int p = blockIdx.x * blockDim.x + threadIdx.x;
    if (p >= npts) return;

    float2 gxy = reinterpret_cast<const float2*>(coord)[p];
    float x = (gxy.x + 1.0f) * (IMG_W * 0.5f) - 0.5f;
    float y = (gxy.y + 1.0f) * (IMG_H * 0.5f) - 0.5f;
    float x0f = floorf(x), y0f = floorf(y);
    float wx1 = x - x0f, wy1 = y - y0f;
    float wx0 = 1.0f - wx1, wy0 = 1.0f - wy1;

    int x0 = (int)x0f, y0 = (int)y0f;
    int x1 = x0 + 1,  y1 = y0 + 1;

    float vx0 = (x0 >= 0 && x0 < IMG_W) ? 1.0f : 0.0f;
    float vx1 = (x1 >= 0 && x1 < IMG_W) ? 1.0f : 0.0f;
    float vy0 = (y0 >= 0 && y0 < IMG_H) ? 1.0f : 0.0f;
    float vy1 = (y1 >= 0 && y1 < IMG_H) ? 1.0f : 0.0f;

    int cx0 = min(max(x0, 0), IMG_W - 1);
    int cx1 = min(max(x1, 0), IMG_W - 1);
    int cy0 = min(max(y0, 0), IMG_H - 1);
    int cy1 = min(max(y1, 0), IMG_H - 1);

    float w00 = wx0 * vx0 * wy0 * vy0;
    float w10 = wx1 * vx1 * wy0 * vy0;
    float w01 = wx0 * vx0 * wy1 * vy1;
    float w11 = wx1 * vx1 * wy1 * vy1;

    const uint2* img = (const uint2*)g_imgh;       // one pixel = 8B
    uint2 r00 = __ldg(&img[(size_t)cy0 * IMG_W + cx0]);
    uint2 r10 = __ldg(&img[(size_t)cy0 * IMG_W + cx1]);
    uint2 r01 = __ldg(&img[(size_t)cy1 * IMG_W + cx0]);
    uint2 r11 = __ldg(&img[(size_t)cy1 * IMG_W + cx1]);

    float2 a00 = __half22float2(*(__half2*)&r00.x);
    float2 b00 = __half22float2(*(__half2*)&r00.y);
    float2 a10 = __half22float2(*(__half2*)&r10.x);
    float2 b10 = __half22float2(*(__half2*)&r10.y);
    float2 a01 = __half22float2(*(__half2*)&r01.x);
    float2 b01 = __half22float2(*(__half2*)&r01.y);
    float2 a11 = __half22float2(*(__half2*)&r11.x);
    float2 b11 = __half22float2(*(__half2*)&r11.y);

    out[(size_t)p * 3 + 0] = w00 * a00.x + w10 * a10.x + w01 * a01.x + w11 * a11.x;
    out[(size_t)p * 3 + 1] = w00 * a00.y + w10 * a10.y + w01 * a01.y + w11 * a11.y;
    out[(size_t)p * 3 + 2] = w00 * b00.x + w10 * b10.x + w01 * b01.x + w11 * b11.x;
}

// =====================================================================
extern "C" void kernel_launch(void* const* d_in, const int* in_sizes, int n_in,
                              void* d_out, int out_size) {
    const float* rank1 = (const float*)d_in[0];
    const float* rank2 = (const float*)d_in[1];
    const float* sigma = (const float*)d_in[2];
    const float* coord = (const float*)d_in[3];
    float* out = (float*)d_out;

    const int npts = in_sizes[3] / 2;

    k_blur2<<<6 * RANKS, 256>>>(rank1, rank2, sigma);

    dim3 tgrid(IMG_W / 32, RANKS / 32, 6);
    k_split_t<<<tgrid, dim3(32, 8)>>>();

    cudaFuncSetAttribute(k_mma_gemm, cudaFuncAttributeMaxDynamicSharedMemorySize, SM_TOTAL);
    dim3 ggrid(IMG_W / 64, IMG_H / 128, 3);
    k_mma_gemm<<<ggrid, 256, SM_TOTAL>>>();

    k_sample<<<(npts + 255) / 256, 256>>>(coord, out, npts);
    (void)n_in; (void)out_size;
}

// round 8
// speedup vs baseline: 2.4017x; 1.1373x over previous
#include <cuda_runtime.h>
#include <cuda_fp16.h>
#include <math.h>
#include <stdint.h>

#define IMG_W 2048
#define IMG_H 2048
#define RANKS 128
#define KSZ   101
#define KHALF 50

// ---------------- scratch (__device__ globals; no allocation allowed) ----------------
__device__ float g_r1b[3 * RANKS * IMG_W];            // blurred rank1 fp32 [c][r][w]
__device__ float g_r2b[3 * RANKS * IMG_H];            // blurred rank2 fp32 [c][r][h]
// transposed fp16 factors, K-contiguous: [c][x][r]
__device__ __half g_Bt[3 * IMG_W * RANKS];            // from rank1 (w axis) -> GEMM B
__device__ __half g_At[3 * IMG_H * RANKS];            // from rank2 (h axis) -> GEMM A
__device__ __half g_imgh[(size_t)IMG_H * IMG_W * 4];  // fp16 interleaved [h][w][4], 32MB

__device__ __forceinline__ uint32_t smem_u32(const void* p) {
    uint32_t a;
    asm("{ .reg .u64 t; cvta.to.shared.u64 t, %1; cvt.u32.u64 %0, t; }" : "=r"(a) : "l"(p));
    return a;
}

// =====================================================================
// K1: 1D blur (SAME, zero pad), both inputs in one launch.
// =====================================================================
#define PAD    54
#define SROWSZ 2160
#define KWPAD  104

__global__ __launch_bounds__(256) void k_blur2(const float* __restrict__ rank1,
                                               const float* __restrict__ rank2,
                                               const float* __restrict__ sigma_p) {
    __shared__ __align__(16) float srow[SROWSZ];
    __shared__ __align__(16) float skw[KWPAD];
    const int which = blockIdx.x >= 3 * RANKS;
    const int row   = blockIdx.x - which * 3 * RANKS;
    const float* in  = (which ? rank2 : rank1) + (size_t)row * IMG_W;
    float*       out = (which ? g_r2b : g_r1b) + (size_t)row * IMG_W;
    const int tid = threadIdx.x;

    {
        float sigma = *sigma_p;
        float s   = fmaxf(sigma, 0.01f);
        float amp = 1.0f / fmaxf(sigma * 2.50662827463100050242f, 1.0f);
        for (int i = tid; i < KWPAD; i += 256) {
            float v = 0.0f;
            if (i < KSZ) {
                float n = (float)(i - KHALF);
                float t = n / s;
                v = amp * expf(-0.5f * t * t);
            }
            skw[i] = v;
        }
    }
    for (int i = tid; i < SROWSZ; i += 256) {
        int j = i - PAD;
        srow[i] = (j >= 0 && j < IMG_W) ? in[j] : 0.0f;
    }
    __syncthreads();

    #pragma unroll
    for (int grp = 0; grp < 2; grp++) {
        const int w0 = (tid + grp * 256) * 4;
        const float4* sv = (const float4*)&srow[w0 + 4];
        float a0 = 0.f, a1 = 0.f, a2 = 0.f, a3 = 0.f;
        float4 q0 = sv[0];
        #pragma unroll
        for (int t = 0; t < 26; t++) {
            float4 q1 = sv[t + 1];
            float4 kq = *(const float4*)&skw[4 * t];
            a0 = fmaf(kq.x, q0.x, a0); a1 = fmaf(kq.x, q0.y, a1);
            a2 = fmaf(kq.x, q0.z, a2); a3 = fmaf(kq.x, q0.w, a3);
            a0 = fmaf(kq.y, q0.y, a0); a1 = fmaf(kq.y, q0.z, a1);
            a2 = fmaf(kq.y, q0.w, a2); a3 = fmaf(kq.y, q1.x, a3);
            a0 = fmaf(kq.z, q0.z, a0); a1 = fmaf(kq.z, q0.w, a1);
            a2 = fmaf(kq.z, q1.x, a2); a3 = fmaf(kq.z, q1.y, a3);
            a0 = fmaf(kq.w, q0.w, a0); a1 = fmaf(kq.w, q1.x, a1);
            a2 = fmaf(kq.w, q1.y, a2); a3 = fmaf(kq.w, q1.z, a3);
            q0 = q1;
        }
        float4 res = make_float4(a0, a1, a2, a3);
        *(float4*)&out[w0] = res;
    }
}

// =====================================================================
// K2: transpose + fp16 convert. [c][r][x] fp32 -> [c][x][r] fp16
// grid.z = 6: z%3 = channel, z/3 = which
// =====================================================================
__global__ __launch_bounds__(256) void k_split_t() {
    __shared__ float t[32][33];
    const int c     = blockIdx.z % 3;
    const int which = blockIdx.z / 3;
    const int x0 = blockIdx.x * 32;
    const int r0 = blockIdx.y * 32;
    const float* src = (which ? g_r2b : g_r1b) + (size_t)c * RANKS * IMG_W;
    __half* dst = (which ? g_At : g_Bt) + (size_t)c * IMG_W * RANKS;

    const int tx = threadIdx.x;
    const int ty = threadIdx.y;
    #pragma unroll
    for (int i = 0; i < 32; i += 8)
        t[ty + i][tx] = src[(size_t)(r0 + ty + i) * IMG_W + (x0 + tx)];
    __syncthreads();
    #pragma unroll
    for (int i = 0; i < 32; i += 8) {
        float v = t[tx][ty + i];
        dst[(size_t)(x0 + ty + i) * RANKS + (r0 + tx)] = __float2half_rn(v);
    }
}

// =====================================================================
// K3: mma.sync fp16 GEMM (fp32 accum), single pass. fp16 image epilogue.
// Block 128(M=h) x 64(N=w), K=128 resident. 8 warps as 4(m) x 2(n).
// =====================================================================
#define KP 136
#define SA 0
#define SB 34816
#define SM_TOTAL 52224

__device__ __forceinline__ void ldm_x4(uint32_t* r, uint32_t addr) {
    asm volatile("ldmatrix.sync.aligned.m8n8.x4.shared.b16 {%0,%1,%2,%3}, [%4];"
                 : "=r"(r[0]), "=r"(r[1]), "=r"(r[2]), "=r"(r[3]) : "r"(addr));
}
__device__ __forceinline__ void mma_f16(float* d, const uint32_t* a, uint32_t b0, uint32_t b1) {
    asm volatile(
        "mma.sync.aligned.m16n8k16.row.col.f32.f16.f16.f32 "
        "{%0,%1,%2,%3}, {%4,%5,%6,%7}, {%8,%9}, {%0,%1,%2,%3};"
        : "+f"(d[0]), "+f"(d[1]), "+f"(d[2]), "+f"(d[3])
        : "r"(a[0]), "r"(a[1]), "r"(a[2]), "r"(a[3]), "r"(b0), "r"(b1));
}

__global__ __launch_bounds__(256, 3) void k_mma_gemm() {
    extern __shared__ char smem[];
    const uint32_t sb = smem_u32(smem);
    const int tid  = threadIdx.x;
    const int wid  = tid >> 5;
    const int lane = tid & 31;
    const int mw = wid & 3;
    const int nw = wid >> 2;
    const int c  = blockIdx.z;
    const int n0 = blockIdx.x * 64;
    const int m0 = blockIdx.y * 128;

    {
        const uint4* srcA = (const uint4*)(g_At + ((size_t)(c * IMG_H + m0)) * RANKS);
        const uint4* srcB = (const uint4*)(g_Bt + ((size_t)(c * IMG_W + n0)) * RANKS);
        #pragma unroll
        for (int it = 0; it < 8; it++) {           // A: 128 rows * 16 chunks
            int idx = tid + it * 256;
            int row = idx >> 4, ch = idx & 15;
            uint32_t off = (uint32_t)row * (KP * 2) + ch * 16;
            *(uint4*)(smem + SA + off) = srcA[(size_t)row * 16 + ch];
        }
        #pragma unroll
        for (int it = 0; it < 4; it++) {           // B: 64 rows * 16 chunks
            int idx = tid + it * 256;
            int row = idx >> 4, ch = idx & 15;
            uint32_t off = (uint32_t)row * (KP * 2) + ch * 16;
            *(uint4*)(smem + SB + off) = srcB[(size_t)row * 16 + ch];
        }
    }
    __syncthreads();

    float d[2][4][4];
    #pragma unroll
    for (int i = 0; i < 2; i++)
        #pragma unroll
        for (int j = 0; j < 4; j++)
            #pragma unroll
            for (int r = 0; r < 4; r++) d[i][j][r] = 0.0f;

    const int a_row = (lane & 15);
    const int a_ko  = (lane >> 4) * 8;
    const int quad  = lane >> 3;
    const int b_row = ((quad >> 1) * 8) + (lane & 7);
    const int b_ko  = (quad & 1) * 8;

    #pragma unroll
    for (int ks = 0; ks < 8; ks++) {
        const int k0 = ks * 16;
        const uint32_t aoff = ((uint32_t)(mw * 32 + a_row) * KP + k0 + a_ko) * 2;
        const uint32_t boff = ((uint32_t)(nw * 32 + b_row) * KP + k0 + b_ko) * 2;
        uint32_t af[2][4], bf[2][4];

        ldm_x4(af[0], sb + SA + aoff);
        ldm_x4(af[1], sb + SA + aoff + 16 * KP * 2);
        ldm_x4(bf[0], sb + SB + boff);
        ldm_x4(bf[1], sb + SB + boff + 16 * KP * 2);
        #pragma unroll
        for (int mt = 0; mt < 2; mt++)
            #pragma unroll
            for (int nt = 0; nt < 4; nt++)
                mma_f16(d[mt][nt], af[mt], bf[nt >> 1][(nt & 1) * 2],
                        bf[nt >> 1][(nt & 1) * 2 + 1]);
    }

    // ---- epilogue: write fp16 channel-interleaved image ----
    const int g = lane >> 2;
    const int t = lane & 3;
    #pragma unroll
    for (int mt = 0; mt < 2; mt++) {
        #pragma unroll
        for (int nt = 0; nt < 4; nt++) {
            int m = m0 + mw * 32 + mt * 16 + g;
            int n = n0 + nw * 32 + nt * 8 + t * 2;
            __half* p0 = g_imgh + ((size_t)m * IMG_W + n) * 4 + c;
            p0[0] = __float2half_rn(d[mt][nt][0]);
            p0[4] = __float2half_rn(d[mt][nt][1]);
            __half* p1 = g_imgh + ((size_t)(m + 8) * IMG_W + n) * 4 + c;
            p1[0] = __float2half_rn(d[mt][nt][2]);
            p1[4] = __float2half_rn(d[mt][nt][3]);
        }
    }
}

// =====================================================================
// K4: bilinear grid sample; ONE 8B load per tap (pixel = 4 x fp16)
// =====================================================================
__global__ __launch_bounds__(256) void k_sample(const float* __restrict__ coord,
                                                float* __restrict__ out, int npts) {
    int p = blockIdx.x * blockDim.x + threadIdx.x;
    if (p >= npts) return;

    float2 gxy = reinterpret_cast<const float2*>(coord)[p];
    float x = (gxy.x + 1.0f) * (IMG_W * 0.5f) - 0.5f;
    float y = (gxy.y + 1.0f) * (IMG_H * 0.5f) - 0.5f;
    float x0f = floorf(x), y0f = floorf(y);
    float wx1 = x - x0f, wy1 = y - y0f;
    float wx0 = 1.0f - wx1, wy0 = 1.0f - wy1;

    int x0 = (int)x0f, y0 = (int)y0f;
    int x1 = x0 + 1,  y1 = y0 + 1;

    float vx0 = (x0 >= 0 && x0 < IMG_W) ? 1.0f : 0.0f;
    float vx1 = (x1 >= 0 && x1 < IMG_W) ? 1.0f : 0.0f;
    float vy0 = (y0 >= 0 && y0 < IMG_H) ? 1.0f : 0.0f;
    float vy1 = (y1 >= 0 && y1 < IMG_H) ? 1.0f : 0.0f;

    int cx0 = min(max(x0, 0), IMG_W - 1);
    int cx1 = min(max(x1, 0), IMG_W - 1);
    int cy0 = min(max(y0, 0), IMG_H - 1);
    int cy1 = min(max(y1, 0), IMG_H - 1);

    float w00 = wx0 * vx0 * wy0 * vy0;
    float w10 = wx1 * vx1 * wy0 * vy0;
    float w01 = wx0 * vx0 * wy1 * vy1;
    float w11 = wx1 * vx1 * wy1 * vy1;

    const uint2* img = (const uint2*)g_imgh;       // one pixel = 8B
    uint2 r00 = __ldg(&img[(size_t)cy0 * IMG_W + cx0]);
    uint2 r10 = __ldg(&img[(size_t)cy0 * IMG_W + cx1]);
    uint2 r01 = __ldg(&img[(size_t)cy1 * IMG_W + cx0]);
    uint2 r11 = __ldg(&img[(size_t)cy1 * IMG_W + cx1]);

    float2 a00 = __half22float2(*(__half2*)&r00.x);
    float2 b00 = __half22float2(*(__half2*)&r00.y);
    float2 a10 = __half22float2(*(__half2*)&r10.x);
    float2 b10 = __half22float2(*(__half2*)&r10.y);
    float2 a01 = __half22float2(*(__half2*)&r01.x);
    float2 b01 = __half22float2(*(__half2*)&r01.y);
    float2 a11 = __half22float2(*(__half2*)&r11.x);
    float2 b11 = __half22float2(*(__half2*)&r11.y);

    out[(size_t)p * 3 + 0] = w00 * a00.x + w10 * a10.x + w01 * a01.x + w11 * a11.x;
    out[(size_t)p * 3 + 1] = w00 * a00.y + w10 * a10.y + w01 * a01.y + w11 * a11.y;
    out[(size_t)p * 3 + 2] = w00 * b00.x + w10 * b10.x + w01 * b01.x + w11 * b11.x;
}

// =====================================================================
extern "C" void kernel_launch(void* const* d_in, const int* in_sizes, int n_in,
                              void* d_out, int out_size) {
    const float* rank1 = (const float*)d_in[0];
    const float* rank2 = (const float*)d_in[1];
    const float* sigma = (const float*)d_in[2];
    const float* coord = (const float*)d_in[3];
    float* out = (float*)d_out;

    const int npts = in_sizes[3] / 2;

    k_blur2<<<6 * RANKS, 256>>>(rank1, rank2, sigma);

    dim3 tgrid(IMG_W / 32, RANKS / 32, 6);
    k_split_t<<<tgrid, dim3(32, 8)>>>();

    cudaFuncSetAttribute(k_mma_gemm, cudaFuncAttributeMaxDynamicSharedMemorySize, SM_TOTAL);
    dim3 ggrid(IMG_W / 64, IMG_H / 128, 3);
    k_mma_gemm<<<ggrid, 256, SM_TOTAL>>>();

    k_sample<<<(npts + 255) / 256, 256>>>(coord, out, npts);
    (void)n_in; (void)out_size;
}